// round 6
// baseline (speedup 1.0000x reference)
#include <cuda_runtime.h>

// Problem constants: B=8, N=2048, D=768, two tensors (H, doc_sents_h)
#define DDIM   768
#define NROWS  32768            // 2 * 8 * 2048 source rows
#define ROW4   512              // float4 per output row (2048/4)
#define TILE_R 8                // output rows per phase-2 block

// Scratch: s_src (bias folded in) and s_dst per (tensor, batch, n)
__device__ float g_src[NROWS];
__device__ float g_dst[NROWS];

// Phase 1: one warp per row. Compute X·wa and X·wb in one pass.
__global__ __launch_bounds__(256) void edge_phase1(
    const float* __restrict__ H,
    const float* __restrict__ Dh,
    const float* __restrict__ W,     // [2*DDIM]: wa then wb
    const float* __restrict__ bptr)  // [1]
{
    int r    = blockIdx.x * 8 + (threadIdx.x >> 5);   // row 0..32767
    int lane = threadIdx.x & 31;
    if (r >= NROWS) return;

    const float* X = (r < NROWS / 2) ? (H  + (size_t)r * DDIM)
                                     : (Dh + (size_t)(r - NROWS / 2) * DDIM);
    const float4* X4  = (const float4*)X;
    const float4* Wa4 = (const float4*)W;
    const float4* Wb4 = (const float4*)(W + DDIM);

    float sa = 0.f, sb = 0.f;
    #pragma unroll
    for (int k = 0; k < 6; k++) {                     // 192 float4 per row / 32 lanes
        int idx = lane + k * 32;
        float4 x  = X4[idx];
        float4 wa = __ldg(&Wa4[idx]);
        float4 wb = __ldg(&Wb4[idx]);
        sa = fmaf(x.x, wa.x, fmaf(x.y, wa.y, fmaf(x.z, wa.z, fmaf(x.w, wa.w, sa))));
        sb = fmaf(x.x, wb.x, fmaf(x.y, wb.y, fmaf(x.z, wb.z, fmaf(x.w, wb.w, sb))));
    }
    #pragma unroll
    for (int off = 16; off; off >>= 1) {
        sa += __shfl_xor_sync(0xffffffffu, sa, off);
        sb += __shfl_xor_sync(0xffffffffu, sb, off);
    }
    if (lane == 0) {
        g_src[r] = sa + __ldg(bptr);   // fold bias into the src term
        g_dst[r] = sb;
    }
}

// Phase 2, tiled: each block covers TILE_R=8 consecutive output rows (same
// group, since 2048 % 8 == 0) across the FULL row width. Each thread loads
// its two sd float4 ONCE and reuses them for all 8 rows -> ~8x fewer L1
// load wavefronts than the untiled version. All index math is 32-bit.
__global__ __launch_bounds__(256) void edge_phase2(float4* __restrict__ out)
{
    const float*  __restrict__ src  = g_src;
    const float4* __restrict__ dst4 = (const float4*)g_dst;

    unsigned tid  = threadIdx.x;
    unsigned row0 = blockIdx.x * TILE_R;              // 4096 blocks * 8 = 32768 rows
    unsigned grp9 = (row0 >> 11) << 9;                // group base in float4 units

    // Two sd operands, reused across all 8 rows
    float4 sdA = __ldg(&dst4[grp9 + tid]);
    float4 sdB = __ldg(&dst4[grp9 + tid + 256]);

    // Per-row src scalars (uniform within block; L1 broadcast)
    float si[TILE_R];
    #pragma unroll
    for (int g = 0; g < TILE_R; g++)
        si[g] = __ldg(&src[row0 + g]);

    #pragma unroll
    for (int g = 0; g < TILE_R; g++) {
        unsigned base = (row0 + g) * ROW4;
        float s = si[g];
        float4 oA, oB;
        oA.x = fmaxf(s + sdA.x, 0.f); oA.y = fmaxf(s + sdA.y, 0.f);
        oA.z = fmaxf(s + sdA.z, 0.f); oA.w = fmaxf(s + sdA.w, 0.f);
        oB.x = fmaxf(s + sdB.x, 0.f); oB.y = fmaxf(s + sdB.y, 0.f);
        oB.z = fmaxf(s + sdB.z, 0.f); oB.w = fmaxf(s + sdB.w, 0.f);
        out[base + tid]       = oA;
        out[base + tid + 256] = oB;
    }
}

extern "C" void kernel_launch(void* const* d_in, const int* in_sizes, int n_in,
                              void* d_out, int out_size)
{
    const float* H  = (const float*)d_in[0];
    const float* Dh = (const float*)d_in[1];
    const float* W  = (const float*)d_in[2];
    const float* b  = (const float*)d_in[3];
    float4* out = (float4*)d_out;

    edge_phase1<<<4096, 256>>>(H, Dh, W, b);   // 32768 rows, 8 warps/block
    edge_phase2<<<4096, 256>>>(out);           // 4096 blocks * 8 rows * 512 float4
}

// round 7
// speedup vs baseline: 1.0645x; 1.0645x over previous
#include <cuda_runtime.h>

// Problem constants: B=8, N=2048, D=768, two tensors (H, doc_sents_h)
#define DDIM   768
#define NROWS  32768            // 2 * 8 * 2048 source rows
#define ROW4   512              // float4 per output row (2048/4)
#define TOTAL4 16777216LL       // total float4 stores

// Scratch: s_src (bias folded in) and s_dst per (tensor, batch, n)
__device__ float g_src[NROWS];
__device__ float g_dst[NROWS];

// Phase 1: one warp per row. Compute X·wa and X·wb in one pass.
// X is read exactly once -> streaming loads (.cs) to avoid polluting L2.
__global__ __launch_bounds__(256) void edge_phase1(
    const float* __restrict__ H,
    const float* __restrict__ Dh,
    const float* __restrict__ W,     // [2*DDIM]: wa then wb
    const float* __restrict__ bptr)  // [1]
{
    int r    = blockIdx.x * 8 + (threadIdx.x >> 5);   // row 0..32767
    int lane = threadIdx.x & 31;
    if (r >= NROWS) return;

    const float* X = (r < NROWS / 2) ? (H  + (size_t)r * DDIM)
                                     : (Dh + (size_t)(r - NROWS / 2) * DDIM);
    const float4* X4  = (const float4*)X;
    const float4* Wa4 = (const float4*)W;
    const float4* Wb4 = (const float4*)(W + DDIM);

    float sa = 0.f, sb = 0.f;
    #pragma unroll
    for (int k = 0; k < 6; k++) {                     // 192 float4 per row / 32 lanes
        int idx = lane + k * 32;
        float4 x  = __ldcs(&X4[idx]);                 // streaming: read-once data
        float4 wa = __ldg(&Wa4[idx]);
        float4 wb = __ldg(&Wb4[idx]);
        sa = fmaf(x.x, wa.x, fmaf(x.y, wa.y, fmaf(x.z, wa.z, fmaf(x.w, wa.w, sa))));
        sb = fmaf(x.x, wb.x, fmaf(x.y, wb.y, fmaf(x.z, wb.z, fmaf(x.w, wb.w, sb))));
    }
    #pragma unroll
    for (int off = 16; off; off >>= 1) {
        sa += __shfl_xor_sync(0xffffffffu, sa, off);
        sb += __shfl_xor_sync(0xffffffffu, sb, off);
    }
    if (lane == 0) {
        g_src[r] = sa + __ldg(bptr);   // fold bias into the src term
        g_dst[r] = sb;
    }
}

// Phase 2 (round-5 contiguous layout): each block writes 1024 CONSECUTIVE
// float4 (16 KB). Output is write-once -> streaming stores (.cs).
__global__ __launch_bounds__(256) void edge_phase2(float4* __restrict__ out)
{
    const float*  __restrict__ src  = g_src;
    const float4* __restrict__ dst4 = (const float4*)g_dst;

    unsigned base = blockIdx.x * 1024u;               // 16384 blocks * 1024 = TOTAL4
    #pragma unroll
    for (int it = 0; it < 4; it++) {
        unsigned v   = base + it * 256u + threadIdx.x;
        unsigned row = v >> 9;                        // /ROW4
        unsigned j4  = v & (ROW4 - 1);
        float  si = __ldg(&src[row]);
        float4 sd = __ldg(&dst4[((row >> 11) << 9) + j4]);  // group = row/2048
        float4 o;
        o.x = fmaxf(si + sd.x, 0.f);
        o.y = fmaxf(si + sd.y, 0.f);
        o.z = fmaxf(si + sd.z, 0.f);
        o.w = fmaxf(si + sd.w, 0.f);
        __stcs(&out[v], o);                           // streaming store: write-once data
    }
}

extern "C" void kernel_launch(void* const* d_in, const int* in_sizes, int n_in,
                              void* d_out, int out_size)
{
    const float* H  = (const float*)d_in[0];
    const float* Dh = (const float*)d_in[1];
    const float* W  = (const float*)d_in[2];
    const float* b  = (const float*)d_in[3];
    float4* out = (float4*)d_out;

    edge_phase1<<<4096, 256>>>(H, Dh, W, b);   // 32768 rows, 8 warps/block
    edge_phase2<<<16384, 256>>>(out);          // contiguous 16 KB per block
}